// round 6
// baseline (speedup 1.0000x reference)
#include <cuda_runtime.h>
#include <cstdint>

// out[t, h] = W[h, seq[t]] + b[h]
// seq: int32 [n_tok], W: fp32 [H, V] row-major, b: fp32 [H], out: fp32 [n_tok, H]
//
// Pipeline (2 launches):
//  1) fused_sort : hist + scan + scatter in ONE kernel. grid=128 blocks
//     (<= 148 SMs -> all co-resident in wave 1, so global spin-waits are
//     deadlock-free). Protocol:
//       phase A: all blocks histogram (global atomics), fence, bump done1
//       phase B: block 0 spins for done1==NB, scans 6283 buckets alone,
//                re-zeroes g_hist (leaves state clean for next invocation),
//                publishes flag
//       phase C: all blocks spin on flag, then scatter their chunk
//       reset  : last block through done2 resets done1/flag/done2 ->
//                identical device state every graph replay (deterministic)
//  2) gather : unchanged from R5 (51.8us @ 71.8% DRAM): lanes-along-sorted-v
//     loads, padded-SMEM transpose, coalesced streaming stores.

#define H_DIM 1024
#define TOK_PER_BLK 32
#define THREADS 256
#define HCHUNK 128
#define NCHUNK (H_DIM / HCHUNK)   // 8

#define MAX_N 65536
#define MAX_BUCKETS 8192
#define SORT_BLOCKS 128            // <= 148 -> resident grid, spin-safe
#define SORT_THREADS 256
#define BUCKETS_PER_T 25           // 256*25 = 6400 >= 6283

__device__ int g_hist[MAX_BUCKETS];   // zero at load; fused_sort re-zeroes
__device__ int g_off[MAX_BUCKETS];
__device__ int g_sorted_v[MAX_N];
__device__ int g_sorted_t[MAX_N];

__device__ volatile int g_done1 = 0;  // hist completions
__device__ volatile int g_flag  = 0;  // scan published
__device__ volatile int g_done2 = 0;  // scatter completions

// ---------------- fused sort ----------------

__global__ __launch_bounds__(SORT_THREADS)
void fused_sort_kernel(const int* __restrict__ seq, int n, int nbuckets) {
    const int tid = threadIdx.x;
    const int gsz = gridDim.x * blockDim.x;
    const int gid = blockIdx.x * blockDim.x + tid;

    // ---- phase A: histogram (grid-stride) ----
    for (int i = gid; i < n; i += gsz)
        atomicAdd(&g_hist[seq[i] >> 3], 1);

    __syncthreads();
    if (tid == 0) {
        __threadfence();
        atomicAdd((int*)&g_done1, 1);
    }

    // ---- phase B: block 0 performs the scan alone ----
    if (blockIdx.x == 0) {
        if (tid == 0) {
            while (atomicAdd((int*)&g_done1, 0) != gridDim.x) __nanosleep(64);
            __threadfence();
        }
        __syncthreads();

        __shared__ int warp_sums[8];
        const int lane = tid & 31;
        const int w    = tid >> 5;

        int vals[BUCKETS_PER_T];
        int local = 0;
        #pragma unroll
        for (int i = 0; i < BUCKETS_PER_T; i++) {
            int idx = tid * BUCKETS_PER_T + i;
            vals[i] = (idx < nbuckets) ? g_hist[idx] : 0;
            local += vals[i];
        }

        int x = local;
        #pragma unroll
        for (int d = 1; d < 32; d <<= 1) {
            int y = __shfl_up_sync(0xFFFFFFFFu, x, d);
            if (lane >= d) x += y;
        }
        if (lane == 31) warp_sums[w] = x;
        __syncthreads();

        if (w == 0) {
            int s = (lane < 8) ? warp_sums[lane] : 0;
            #pragma unroll
            for (int d = 1; d < 8; d <<= 1) {
                int y = __shfl_up_sync(0xFFFFFFFFu, s, d);
                if (lane >= d) s += y;
            }
            if (lane < 8) warp_sums[lane] = s;
        }
        __syncthreads();

        int run = (w > 0 ? warp_sums[w - 1] : 0) + (x - local);
        #pragma unroll
        for (int i = 0; i < BUCKETS_PER_T; i++) {
            int idx = tid * BUCKETS_PER_T + i;
            if (idx < nbuckets) {
                g_off[idx]  = run;
                g_hist[idx] = 0;           // clean for next invocation
            }
            run += vals[i];
        }

        __syncthreads();
        if (tid == 0) {
            __threadfence();
            atomicExch((int*)&g_flag, 1);  // publish
        }
    }

    // ---- phase C: wait for scan, then scatter ----
    if (tid == 0) {
        while (atomicAdd((int*)&g_flag, 0) == 0) __nanosleep(64);
        __threadfence();
    }
    __syncthreads();

    for (int t = gid; t < n; t += gsz) {
        int v = seq[t];
        int pos = atomicAdd(&g_off[v >> 3], 1);
        g_sorted_v[pos] = v;
        g_sorted_t[pos] = t;
    }

    // ---- reset protocol state for the next invocation ----
    __syncthreads();
    if (tid == 0) {
        __threadfence();
        int old = atomicAdd((int*)&g_done2, 1);
        if (old == gridDim.x - 1) {
            g_done1 = 0;
            g_flag  = 0;
            g_done2 = 0;
            __threadfence();
        }
    }
}

// ---------------- main gather (unchanged from R5) ----------------

__global__ __launch_bounds__(THREADS, 8)
void onehot_gather_xpose_kernel(const float* __restrict__ W,
                                const float* __restrict__ bias,
                                float* __restrict__ out,
                                int n_tok, int V) {
    __shared__ float s_w[HCHUNK][TOK_PER_BLK + 1];  // pad -> conflict-free both phases
    __shared__ int s_t[TOK_PER_BLK];
    __shared__ int s_v[TOK_PER_BLK];

    const int tid  = threadIdx.x;
    const int lane = tid & 31;
    const int w    = tid >> 5;
    const int base = blockIdx.x * TOK_PER_BLK;

    if (tid < TOK_PER_BLK) {
        int j = base + tid;
        s_v[tid] = (j < n_tok) ? g_sorted_v[j] : 0;   // clamp: valid addr
        s_t[tid] = (j < n_tok) ? g_sorted_t[j] : -1;  // -1 -> skip store
    }
    __syncthreads();

    // Load phase: lane owns token 'lane' (sorted values -> few sectors/warp).
    const int my_v = s_v[lane];

    // Store phase: warp w owns tokens 4w..4w+3.
    int st_t[4];
    #pragma unroll
    for (int q = 0; q < 4; q++) st_t[q] = s_t[(w << 2) + q];

    for (int c = 0; c < NCHUNK; c++) {
        const int h_base = c * HCHUNK;

        // ---- load phase: 16 independent gathers per thread ----
        #pragma unroll
        for (int i = 0; i < 16; i++) {
            int h_local = (i << 3) + w;  // warp w covers h_local = w, w+8, ...
            float val = __ldg(W + (size_t)(h_base + h_local) * (size_t)V + my_v);
            s_w[h_local][lane] = val;    // stride-1 across lanes: conflict-free
        }

        // bias for this lane's 4 h positions in the chunk
        float bl[4];
        #pragma unroll
        for (int hs = 0; hs < 4; hs++)
            bl[hs] = __ldg(bias + h_base + (hs << 5) + lane);

        __syncthreads();

        // ---- store phase: coalesced 128B rows ----
        #pragma unroll
        for (int q = 0; q < 4; q++) {
            const int j = (w << 2) + q;
            const int t = st_t[q];
            if (t < 0) continue;
            float* dst = out + (size_t)t * H_DIM + h_base;
            #pragma unroll
            for (int hs = 0; hs < 4; hs++) {
                int h_local = (hs << 5) + lane;
                float r = s_w[h_local][j] + bl[hs];  // stride-33: conflict-free
                __stcs(dst + h_local, r);
            }
        }
        __syncthreads();
    }
}

// ---------------- launch ----------------

extern "C" void kernel_launch(void* const* d_in, const int* in_sizes, int n_in,
                              void* d_out, int out_size) {
    const int*   seq  = (const int*)d_in[0];
    const float* W    = (const float*)d_in[1];
    const float* bias = (const float*)d_in[2];
    float*       out  = (float*)d_out;

    const int n_tok = in_sizes[0];            // 32768
    const int H     = in_sizes[2];            // 1024
    const int V     = in_sizes[1] / H;        // 50257
    const int nbuckets = (V + 7) >> 3;        // 6283
    (void)out_size; (void)n_in;

    fused_sort_kernel<<<SORT_BLOCKS, SORT_THREADS>>>(seq, n_tok, nbuckets);

    const int blocks = (n_tok + TOK_PER_BLK - 1) / TOK_PER_BLK;
    onehot_gather_xpose_kernel<<<blocks, THREADS>>>(W, bias, out, n_tok, V);
}

// round 7
// speedup vs baseline: 1.0231x; 1.0231x over previous
#include <cuda_runtime.h>
#include <cstdint>

// out[t, h] = W[h, seq[t]] + b[h]
// seq: int32 [n_tok], W: fp32 [H, V] row-major, b: fp32 [H], out: fp32 [n_tok, H]
//
// Pipeline (3 launches):
//  1) hist+scan : all blocks histogram v>>3 buckets (global atomics); the
//     LAST block to finish (atomic ticket -- nobody spins) scans the 6283
//     buckets into g_off, re-zeroes g_hist, and resets the ticket. Device
//     state is identical after every invocation -> graph-replay safe.
//  2) scatter   : counting-sort packed (v,t) pairs by bucket.
//  3) gather    : unchanged from R5 (51.8us @ 71% DRAM): lanes-along-sorted-v
//     loads, padded-SMEM transpose, coalesced streaming stores.

#define H_DIM 1024
#define TOK_PER_BLK 32
#define THREADS 256
#define HCHUNK 128
#define NCHUNK (H_DIM / HCHUNK)   // 8

#define MAX_N 65536
#define MAX_BUCKETS 8192
#define HIST_BLOCKS 128
#define HIST_THREADS 256
#define BUCKETS_PER_T 25           // 256*25 = 6400 >= 6283

__device__ int g_hist[MAX_BUCKETS];   // zero at load; hist+scan re-zeroes
__device__ int g_off[MAX_BUCKETS];
__device__ int2 g_sorted[MAX_N];      // .x = v, .y = t
__device__ int g_ticket = 0;          // last-block election; reset each call

// ---------------- kernel 1: hist + last-block scan ----------------

__global__ __launch_bounds__(HIST_THREADS)
void hist_scan_kernel(const int* __restrict__ seq, int n, int nbuckets) {
    const int tid = threadIdx.x;
    const int gsz = gridDim.x * blockDim.x;

    for (int i = blockIdx.x * blockDim.x + tid; i < n; i += gsz)
        atomicAdd(&g_hist[seq[i] >> 3], 1);

    // elect the last block to finish (no waiting for the others)
    __shared__ int s_last;
    __syncthreads();
    if (tid == 0) {
        __threadfence();
        s_last = (atomicAdd(&g_ticket, 1) == gridDim.x - 1);
    }
    __syncthreads();
    if (!s_last) return;

    // ---- last block: scan 6283 buckets, zero g_hist, reset ticket ----
    __shared__ int warp_sums[8];
    const int lane = tid & 31;
    const int w    = tid >> 5;

    int vals[BUCKETS_PER_T];
    int local = 0;
    #pragma unroll
    for (int i = 0; i < BUCKETS_PER_T; i++) {
        int idx = tid * BUCKETS_PER_T + i;
        vals[i] = (idx < nbuckets) ? __ldcg(&g_hist[idx]) : 0;  // L2 (atomics live there)
        local += vals[i];
    }

    int x = local;
    #pragma unroll
    for (int d = 1; d < 32; d <<= 1) {
        int y = __shfl_up_sync(0xFFFFFFFFu, x, d);
        if (lane >= d) x += y;
    }
    if (lane == 31) warp_sums[w] = x;
    __syncthreads();

    if (w == 0) {
        int s = (lane < 8) ? warp_sums[lane] : 0;
        #pragma unroll
        for (int d = 1; d < 8; d <<= 1) {
            int y = __shfl_up_sync(0xFFFFFFFFu, s, d);
            if (lane >= d) s += y;
        }
        if (lane < 8) warp_sums[lane] = s;
    }
    __syncthreads();

    int run = (w > 0 ? warp_sums[w - 1] : 0) + (x - local);
    #pragma unroll
    for (int i = 0; i < BUCKETS_PER_T; i++) {
        int idx = tid * BUCKETS_PER_T + i;
        if (idx < nbuckets) {
            g_off[idx]  = run;
            g_hist[idx] = 0;          // clean for next invocation
        }
        run += vals[i];
    }

    if (tid == 0) g_ticket = 0;       // clean for next invocation
}

// ---------------- kernel 2: scatter ----------------

__global__ void scatter_kernel(const int* __restrict__ seq, int n) {
    int t = blockIdx.x * blockDim.x + threadIdx.x;
    if (t < n) {
        int v = seq[t];
        int pos = atomicAdd(&g_off[v >> 3], 1);
        g_sorted[pos] = make_int2(v, t);
    }
}

// ---------------- kernel 3: main gather (R5-proven) ----------------

__global__ __launch_bounds__(THREADS, 8)
void onehot_gather_xpose_kernel(const float* __restrict__ W,
                                const float* __restrict__ bias,
                                float* __restrict__ out,
                                int n_tok, int V) {
    __shared__ float s_w[HCHUNK][TOK_PER_BLK + 1];  // pad -> conflict-free both phases
    __shared__ int s_t[TOK_PER_BLK];
    __shared__ int s_v[TOK_PER_BLK];

    const int tid  = threadIdx.x;
    const int lane = tid & 31;
    const int w    = tid >> 5;
    const int base = blockIdx.x * TOK_PER_BLK;

    if (tid < TOK_PER_BLK) {
        int j = base + tid;
        int2 vt = (j < n_tok) ? g_sorted[j] : make_int2(0, -1);
        s_v[tid] = vt.x;   // clamp: valid addr when padding
        s_t[tid] = vt.y;   // -1 -> skip store
    }
    __syncthreads();

    // Load phase: lane owns token 'lane' (sorted values -> few sectors/warp).
    const int my_v = s_v[lane];

    // Store phase: warp w owns tokens 4w..4w+3.
    int st_t[4];
    #pragma unroll
    for (int q = 0; q < 4; q++) st_t[q] = s_t[(w << 2) + q];

    for (int c = 0; c < NCHUNK; c++) {
        const int h_base = c * HCHUNK;

        // ---- load phase: 16 independent gathers per thread ----
        #pragma unroll
        for (int i = 0; i < 16; i++) {
            int h_local = (i << 3) + w;  // warp w covers h_local = w, w+8, ...
            float val = __ldg(W + (size_t)(h_base + h_local) * (size_t)V + my_v);
            s_w[h_local][lane] = val;    // stride-1 across lanes: conflict-free
        }

        // bias for this lane's 4 h positions in the chunk
        float bl[4];
        #pragma unroll
        for (int hs = 0; hs < 4; hs++)
            bl[hs] = __ldg(bias + h_base + (hs << 5) + lane);

        __syncthreads();

        // ---- store phase: coalesced 128B rows ----
        #pragma unroll
        for (int q = 0; q < 4; q++) {
            const int j = (w << 2) + q;
            const int t = st_t[q];
            if (t < 0) continue;
            float* dst = out + (size_t)t * H_DIM + h_base;
            #pragma unroll
            for (int hs = 0; hs < 4; hs++) {
                int h_local = (hs << 5) + lane;
                float r = s_w[h_local][j] + bl[hs];  // stride-33: conflict-free
                __stcs(dst + h_local, r);
            }
        }
        __syncthreads();
    }
}

// ---------------- launch ----------------

extern "C" void kernel_launch(void* const* d_in, const int* in_sizes, int n_in,
                              void* d_out, int out_size) {
    const int*   seq  = (const int*)d_in[0];
    const float* W    = (const float*)d_in[1];
    const float* bias = (const float*)d_in[2];
    float*       out  = (float*)d_out;

    const int n_tok = in_sizes[0];            // 32768
    const int H     = in_sizes[2];            // 1024
    const int V     = in_sizes[1] / H;        // 50257
    const int nbuckets = (V + 7) >> 3;        // 6283
    (void)out_size; (void)n_in;

    hist_scan_kernel<<<HIST_BLOCKS, HIST_THREADS>>>(seq, n_tok, nbuckets);
    scatter_kernel<<<(n_tok + 255) / 256, 256>>>(seq, n_tok);

    const int blocks = (n_tok + TOK_PER_BLK - 1) / TOK_PER_BLK;
    onehot_gather_xpose_kernel<<<blocks, THREADS>>>(W, bias, out, n_tok, V);
}